// round 1
// baseline (speedup 1.0000x reference)
#include <cuda_runtime.h>

#define NB   512
#define NPG  256
#define KSEL 60
#define HID  128
#define EPG  4096
#define NTOT 131072
#define ETOT 2097152
#define TLD  385
#define TLDP 388
#define XS   260   // transposed-x row stride (floats), padded for bank spread + f4 align
#define HSD  132   // h row stride (floats)

#define XBUF_F 33792   // max(128*260, 256*132)
#define WSH_F  16384
#define CSRN_F 4096
#define SMEM_BYTES ((XBUF_F + WSH_F + CSRN_F) * 4 + EPG * 2 + 4 * 1024 + 512 + 256)

// per-node concat features [NTOT][388] (385 used, padded for float4 alignment)
__device__ float g_xcat[(size_t)NTOT * TLDP];

__global__ void __launch_bounds__(512, 1) dgcnn_fused(
    const float* __restrict__ z_table,
    const float* __restrict__ W0, const float* __restrict__ b0,
    const float* __restrict__ W1, const float* __restrict__ b1,
    const float* __restrict__ W2, const float* __restrict__ b2,
    const float* __restrict__ W3, const float* __restrict__ b3,
    const float* __restrict__ c1w, const float* __restrict__ c1b,
    const float* __restrict__ c2w, const float* __restrict__ c2b,
    const float* __restrict__ l1w, const float* __restrict__ l1b,
    const float* __restrict__ l2w, const float* __restrict__ l2b,
    const float* __restrict__ ew,  const int* __restrict__ zz,
    const int* __restrict__ eidx,
    float* __restrict__ out)
{
    extern __shared__ float sm[];
    float* xbuf = sm;                                   // 33792 f (x^T / h / pooled)
    float* Wsh  = xbuf + XBUF_F;                        // 16384 f (W / conv weights)
    float* csrn = Wsh + WSH_F;                          // 4096 f  (edge norms / head bufs)
    unsigned short* csrs = (unsigned short*)(csrn + CSRN_F); // 4096 u16 (edge src local)
    int*   row_end = (int*)(csrs + EPG);                // 256
    int*   cursor  = row_end + NPG;                     // 256 (reused as h3)
    float* dinv    = (float*)(cursor + NPG);            // 256
    float* x3      = dinv + NPG;                        // 256 (reused: c1b/c2b)
    float* bsh     = x3 + NPG;                          // 128 (layer bias / W3)
    int*   sel     = (int*)(bsh + HID);                 // 64

    const int g     = blockIdx.x;
    const int tid   = threadIdx.x;
    const int base  = g * NPG;
    const int ebase = g * EPG;

    // ---------------- degrees (with self loop) + in-degree counts ----------------
    if (tid < NPG) { dinv[tid] = 1.0f; row_end[tid] = 0; }
    __syncthreads();
    for (int e = tid; e < EPG; e += 512) {
        int d = eidx[ETOT + ebase + e] - base;
        atomicAdd(&dinv[d], ew[ebase + e]);
        atomicAdd(&row_end[d], 1);
    }
    __syncthreads();
    if (tid < NPG) dinv[tid] = rsqrtf(dinv[tid]);
    __syncthreads();
    // inclusive scan of counts -> row_end
    for (int s = 1; s < NPG; s <<= 1) {
        int v = 0;
        if (tid < NPG && tid >= s) v = row_end[tid - s];
        __syncthreads();
        if (tid < NPG) row_end[tid] += v;
        __syncthreads();
    }
    if (tid < NPG) cursor[tid] = (tid == 0) ? 0 : row_end[tid - 1];
    __syncthreads();
    // scatter edges into per-dst CSR with precomputed norm
    for (int e = tid; e < EPG; e += 512) {
        int s = eidx[ebase + e] - base;
        int d = eidx[ETOT + ebase + e] - base;
        int pos = atomicAdd(&cursor[d], 1);
        csrs[pos] = (unsigned short)s;
        csrn[pos] = dinv[s] * ew[ebase + e] * dinv[d];
    }
    // ---------------- x0 = z_table[z], stored transposed x^T[k][n] ----------------
    for (int idx = tid; idx < NPG * HID; idx += 512) {
        int n = idx >> 7, k = idx & 127;
        xbuf[k * XS + n] = z_table[zz[base + n] * HID + k];
    }
    __syncthreads();

    const float* Ws[3] = { W0, W1, W2 };
    const float* bs[3] = { b0, b1, b2 };
    float* xcat = g_xcat + (size_t)base * TLDP;

    const int n0 = (tid >> 4) * 8;   // GEMM tile: 8 nodes
    const int c0 = (tid & 15) * 8;   //            8 cols
    const int dn = tid >> 1;         // agg: node
    const int ch = (tid & 1) * 64;   //      64-col half

    // ---------------- layers 0..2 : 128 -> 128 ----------------
    for (int layer = 0; layer < 3; ++layer) {
        for (int i = tid; i < HID * HID; i += 512) Wsh[i] = Ws[layer][i];
        if (tid < HID) bsh[tid] = bs[layer][tid];
        __syncthreads();

        float acc[8][8];
        #pragma unroll
        for (int i = 0; i < 8; ++i)
            #pragma unroll
            for (int j = 0; j < 8; ++j) acc[i][j] = 0.0f;

        for (int k = 0; k < HID; ++k) {
            float4 a0 = *(const float4*)&xbuf[k * XS + n0];
            float4 a1 = *(const float4*)&xbuf[k * XS + n0 + 4];
            float4 w0 = *(const float4*)&Wsh[k * HID + c0];
            float4 w1 = *(const float4*)&Wsh[k * HID + c0 + 4];
            float a[8] = { a0.x, a0.y, a0.z, a0.w, a1.x, a1.y, a1.z, a1.w };
            float w[8] = { w0.x, w0.y, w0.z, w0.w, w1.x, w1.y, w1.z, w1.w };
            #pragma unroll
            for (int i = 0; i < 8; ++i)
                #pragma unroll
                for (int j = 0; j < 8; ++j)
                    acc[i][j] += a[i] * w[j];
        }
        __syncthreads();
        // stash h row-major (reuses x buffer; x fully consumed above)
        #pragma unroll
        for (int i = 0; i < 8; ++i) {
            *(float4*)&xbuf[(n0 + i) * HSD + c0]     = make_float4(acc[i][0], acc[i][1], acc[i][2], acc[i][3]);
            *(float4*)&xbuf[(n0 + i) * HSD + c0 + 4] = make_float4(acc[i][4], acc[i][5], acc[i][6], acc[i][7]);
        }
        __syncthreads();

        // aggregation: x_next[dn][ch..ch+64) = tanh(sum_in h[src]*norm + h[dn]*dinv^2 + b)
        float r[64];
        {
            float sn = dinv[dn] * dinv[dn];
            const float* hp = &xbuf[dn * HSD + ch];
            #pragma unroll
            for (int c = 0; c < 64; ++c) r[c] = hp[c] * sn;
            int s0 = (dn == 0) ? 0 : row_end[dn - 1];
            int s1 = row_end[dn];
            for (int ii = s0; ii < s1; ++ii) {
                int s = csrs[ii];
                float w = csrn[ii];
                const float* sp = &xbuf[s * HSD + ch];
                #pragma unroll
                for (int c = 0; c < 64; c += 4) {
                    float4 hv = *(const float4*)&sp[c];
                    r[c]     += hv.x * w;
                    r[c + 1] += hv.y * w;
                    r[c + 2] += hv.z * w;
                    r[c + 3] += hv.w * w;
                }
            }
            #pragma unroll
            for (int c = 0; c < 64; ++c) r[c] = tanhf(r[c] + bsh[ch + c]);
            float* xr = &xcat[(size_t)dn * TLDP + layer * HID + ch];
            #pragma unroll
            for (int c = 0; c < 64; c += 4)
                *(float4*)&xr[c] = make_float4(r[c], r[c + 1], r[c + 2], r[c + 3]);
        }
        __syncthreads();
        #pragma unroll
        for (int c = 0; c < 64; ++c) xbuf[(ch + c) * XS + dn] = r[c];
        __syncthreads();
    }

    // ---------------- layer 3 : 128 -> 1 ----------------
    if (tid < HID) bsh[tid] = W3[tid];
    __syncthreads();
    float* h3 = (float*)cursor;   // cursor dead
    if (tid < NPG) {
        float acc = 0.0f;
        for (int k = 0; k < HID; ++k) acc += xbuf[k * XS + tid] * bsh[k];
        h3[tid] = acc;
    }
    __syncthreads();
    if (tid < NPG) {
        float acc = h3[tid] * dinv[tid] * dinv[tid];
        int s0 = (tid == 0) ? 0 : row_end[tid - 1];
        int s1 = row_end[tid];
        for (int ii = s0; ii < s1; ++ii)
            acc += h3[csrs[ii]] * csrn[ii];
        float v = tanhf(acc + b3[0]);
        x3[tid] = v;
        xcat[(size_t)tid * TLDP + 384] = v;
    }
    __syncthreads();

    // ---------------- stable descending top-K via rank ----------------
    if (tid < NPG) {
        float v = x3[tid];
        int rank = 0;
        for (int j = 0; j < NPG; ++j) {
            float u = x3[j];
            rank += (u > v) || (u == v && j < tid);
        }
        if (rank < KSEL) sel[rank] = tid;
    }
    __syncthreads();

    // ---------------- head ----------------
    // pooled rows into xbuf [60][TLDP]
    for (int idx = tid; idx < KSEL * TLDP; idx += 512) {
        int k = idx / TLDP, t = idx - k * TLDP;
        xbuf[idx] = (t < TLD) ? xcat[(size_t)sel[k] * TLDP + t] : 0.0f;
    }
    // conv1 weights padded to TLDP; conv2 weights after them
    for (int idx = tid; idx < 16 * TLD; idx += 512) {
        int oc = idx / TLD, t = idx - oc * TLD;
        Wsh[oc * TLDP + t] = c1w[idx];
    }
    float* c2wsh = Wsh + 16 * TLDP;
    for (int idx = tid; idx < 32 * 16 * 5; idx += 512) c2wsh[idx] = c2w[idx];
    if (tid < 16) x3[tid] = c1b[tid];          // x3 dead -> bias stash
    if (tid < 32) x3[16 + tid] = c2b[tid];
    __syncthreads();

    float* out1 = csrn;          // [16][60]
    float* pl   = csrn + 960;    // [16][30]
    float* v2   = csrn + 1440;   // [832]
    float* y1   = csrn + 2272;   // [128]
    float* part = csrn + 2400;   // [512]

    // conv1 (385 -> 16 per pooled node) + relu
    for (int task = tid; task < 16 * KSEL; task += 512) {
        int oc = task / KSEL, k = task - oc * KSEL;
        const float* pr = &xbuf[k * TLDP];
        const float* wr = &Wsh[oc * TLDP];
        float acc = x3[oc];
        for (int t = 0; t < 384; t += 4) {
            float4 pv = *(const float4*)&pr[t];
            float4 wv = *(const float4*)&wr[t];
            acc += pv.x * wv.x + pv.y * wv.y + pv.z * wv.z + pv.w * wv.w;
        }
        acc += pr[384] * wr[384];
        out1[oc * KSEL + k] = fmaxf(acc, 0.0f);
    }
    __syncthreads();
    // maxpool(2,2)
    for (int task = tid; task < 16 * 30; task += 512) {
        int ic = task / 30, j = task - ic * 30;
        pl[ic * 30 + j] = fmaxf(out1[ic * 60 + 2 * j], out1[ic * 60 + 2 * j + 1]);
    }
    __syncthreads();
    // conv2 (16ch k=5 -> 32ch, len 26) + relu, flattened as v2[oc*26+j]
    for (int task = tid; task < 32 * 26; task += 512) {
        int oc = task / 26, j = task - oc * 26;
        float acc = x3[16 + oc];
        #pragma unroll
        for (int ic = 0; ic < 16; ++ic)
            #pragma unroll
            for (int p = 0; p < 5; ++p)
                acc += c2wsh[oc * 80 + ic * 5 + p] * pl[ic * 30 + j + p];
        v2[oc * 26 + j] = fmaxf(acc, 0.0f);
    }
    __syncthreads();
    // lin1: 832 -> 128, relu (4 partial threads per output)
    {
        int o = tid & 127, pt = tid >> 7;
        float acc = 0.0f;
        for (int i = pt * 208; i < pt * 208 + 208; ++i)
            acc += v2[i] * l1w[i * HID + o];
        part[tid] = acc;
    }
    __syncthreads();
    if (tid < HID) {
        float y = part[tid] + part[tid + 128] + part[tid + 256] + part[tid + 384] + l1b[tid];
        y1[tid] = fmaxf(y, 0.0f);
    }
    __syncthreads();
    if (tid < HID) part[tid] = y1[tid] * l2w[tid];
    __syncthreads();
    if (tid == 0) {
        float s = 0.0f;
        for (int i = 0; i < HID; ++i) s += part[i];
        out[g] = s + l2b[0];
    }
}

extern "C" void kernel_launch(void* const* d_in, const int* in_sizes, int n_in,
                              void* d_out, int out_size) {
    (void)in_sizes; (void)n_in; (void)out_size;
    cudaFuncSetAttribute(dgcnn_fused, cudaFuncAttributeMaxDynamicSharedMemorySize, SMEM_BYTES);
    dgcnn_fused<<<NB, 512, SMEM_BYTES>>>(
        (const float*)d_in[0],  (const float*)d_in[1],  (const float*)d_in[2],
        (const float*)d_in[3],  (const float*)d_in[4],  (const float*)d_in[5],
        (const float*)d_in[6],  (const float*)d_in[7],  (const float*)d_in[8],
        (const float*)d_in[9],  (const float*)d_in[10], (const float*)d_in[11],
        (const float*)d_in[12], (const float*)d_in[13], (const float*)d_in[14],
        (const float*)d_in[15], (const float*)d_in[16], (const float*)d_in[17],
        (const int*)d_in[18],   (const int*)d_in[19],
        (float*)d_out);
}